// round 15
// baseline (speedup 1.0000x reference)
#include <cuda_runtime.h>
#include <cuda_bf16.h>
#include <cstdint>
#include <cstddef>

#define B_ 2
#define T_ 2048
#define C_ 2048
#define H_ 16
#define D_ 128
#define EPS_ 1.1920929e-07f

typedef unsigned long long u64t;

// ---------------- mma.sync / ldmatrix / cp.async helpers (sm_80+ portable) --
__device__ __forceinline__ uint32_t smem_u32_of(const void* p) {
    uint32_t a;
    asm("{ .reg .u64 t; cvta.to.shared.u64 t, %1; cvt.u32.u64 %0, t; }"
        : "=r"(a) : "l"(p));
    return a;
}
__device__ __forceinline__ void ldsm4(uint32_t* r, uint32_t addr) {
    asm volatile("ldmatrix.sync.aligned.m8n8.x4.shared.b16 {%0,%1,%2,%3}, [%4];"
        : "=r"(r[0]), "=r"(r[1]), "=r"(r[2]), "=r"(r[3]) : "r"(addr));
}
__device__ __forceinline__ void ldsm4t(uint32_t* r, uint32_t addr) {
    asm volatile("ldmatrix.sync.aligned.m8n8.x4.trans.shared.b16 {%0,%1,%2,%3}, [%4];"
        : "=r"(r[0]), "=r"(r[1]), "=r"(r[2]), "=r"(r[3]) : "r"(addr));
}
__device__ __forceinline__ void mma_bf16(float* c, const uint32_t* a,
                                         uint32_t b0, uint32_t b1) {
    asm volatile(
        "mma.sync.aligned.m16n8k16.row.col.f32.bf16.bf16.f32 "
        "{%0,%1,%2,%3}, {%4,%5,%6,%7}, {%8,%9}, {%0,%1,%2,%3};"
        : "+f"(c[0]), "+f"(c[1]), "+f"(c[2]), "+f"(c[3])
        : "r"(a[0]), "r"(a[1]), "r"(a[2]), "r"(a[3]), "r"(b0), "r"(b1));
}
__device__ __forceinline__ void cp16(uint32_t dst, const void* src) {
    asm volatile("cp.async.cg.shared.global [%0], [%1], 16;"
        :: "r"(dst), "l"(src));
}
#define CP_COMMIT() asm volatile("cp.async.commit_group;" ::: "memory")
#define CP_WAIT1()  asm volatile("cp.async.wait_group 1;" ::: "memory")
#define CP_WAIT0()  asm volatile("cp.async.wait_group 0;" ::: "memory")

// pack two fp32 into bf16x2 hi reg + bf16x2 lo-residual reg
__device__ __forceinline__ void pk_hilo(float a, float b,
                                        uint32_t& h, uint32_t& l) {
    __nv_bfloat16 ha = __float2bfloat16_rn(a);
    __nv_bfloat16 hb = __float2bfloat16_rn(b);
    __nv_bfloat162 hh(ha, hb);
    h = *reinterpret_cast<uint32_t*>(&hh);
    __nv_bfloat162 ll(__float2bfloat16_rn(a - __bfloat162float(ha)),
                      __float2bfloat16_rn(b - __bfloat162float(hb)));
    l = *reinterpret_cast<uint32_t*>(&ll);
}

// ---------------- scratch (static device globals; no runtime alloc) ---------
// pre-split bf16 hi|lo Q/K/V: [B*H, T, 256] (hi 0..127 | lo 128..255)
__device__ __nv_bfloat16 g_q2[(size_t)B_ * H_ * T_ * 256];
__device__ __nv_bfloat16 g_k2[(size_t)B_ * H_ * T_ * 256];
__device__ __nv_bfloat16 g_v2[(size_t)B_ * H_ * T_ * 256];
__device__ float g_cos[(size_t)T_ * D_];
__device__ float g_sin[(size_t)T_ * D_];
// bf16 split operands: A2 [M, 2K] (hi | lo), Bt2 [N, 2K] (hi | lo), K = 2048
__device__ __nv_bfloat16 g_a2[(size_t)(B_ * T_) * (2 * C_)];        // 4096 x 4096
__device__ __nv_bfloat16 g_bt2[(size_t)(3 * C_) * (2 * C_)];        // 6144 x 4096

// ---------------- RoPE tables (double pow -> fp32, mirrors JAX rounding) ----
__global__ void rope_table_kernel(float* __restrict__ ct, float* __restrict__ st) {
    int idx = blockIdx.x * 256 + threadIdx.x;
    if (idx >= T_ * D_) return;
    int t = idx >> 7;
    int d = idx & 127;
    int j = d & 63;
    double inv = 1.0 / pow(1.0e6, (double)j / 64.0);
    float inv_f = (float)inv;
    float freq = (float)t * inv_f;
    ct[idx] = cosf(freq);
    st[idx] = sinf(freq);
}

// ---------------- bf16 hi/lo split: X[M,K] fp32 -> A2[M,2K] bf16 ------------
__global__ void split_rows_kernel(const float* __restrict__ X,
                                  __nv_bfloat16* __restrict__ A2,
                                  int Mrows, int K)
{
    int idx4 = blockIdx.x * 256 + threadIdx.x;
    size_t base = (size_t)idx4 * 4;
    if (base >= (size_t)Mrows * K) return;
    int r = (int)(base / K);
    int c = (int)(base % K);
    float4 v = *(const float4*)&X[base];
    __nv_bfloat16 h0 = __float2bfloat16_rn(v.x);
    __nv_bfloat16 h1 = __float2bfloat16_rn(v.y);
    __nv_bfloat16 h2 = __float2bfloat16_rn(v.z);
    __nv_bfloat16 h3 = __float2bfloat16_rn(v.w);
    __nv_bfloat16 l0 = __float2bfloat16_rn(v.x - __bfloat162float(h0));
    __nv_bfloat16 l1 = __float2bfloat16_rn(v.y - __bfloat162float(h1));
    __nv_bfloat16 l2 = __float2bfloat16_rn(v.z - __bfloat162float(h2));
    __nv_bfloat16 l3 = __float2bfloat16_rn(v.w - __bfloat162float(h3));
    size_t ob = (size_t)r * (2 * K) + c;
    __nv_bfloat162* ph = (__nv_bfloat162*)&A2[ob];
    __nv_bfloat162* pl = (__nv_bfloat162*)&A2[ob + K];
    ph[0] = __nv_bfloat162(h0, h1); ph[1] = __nv_bfloat162(h2, h3);
    pl[0] = __nv_bfloat162(l0, l1); pl[1] = __nv_bfloat162(l2, l3);
}

// ------- transpose + split: W[K,N] fp32 -> Bt2[N,2K] bf16 (K-major) ---------
__global__ void split_trans_kernel(const float* __restrict__ W,
                                   __nv_bfloat16* __restrict__ Bt2,
                                   int K, int N)
{
    __shared__ float tile[32][33];
    const int tx = threadIdx.x & 31, ty = threadIdx.x >> 5;
    const int n0 = blockIdx.x * 32, k0 = blockIdx.y * 32;
    #pragma unroll
    for (int i = 0; i < 4; ++i)
        tile[ty + i * 8][tx] = W[(size_t)(k0 + ty + i * 8) * N + n0 + tx];
    __syncthreads();
    const int K2 = 2 * K;
    #pragma unroll
    for (int i = 0; i < 4; ++i) {
        int n = n0 + ty + i * 8;
        int k = k0 + tx;
        float v = tile[tx][ty + i * 8];
        __nv_bfloat16 h = __float2bfloat16_rn(v);
        __nv_bfloat16 l = __float2bfloat16_rn(v - __bfloat162float(h));
        Bt2[(size_t)n * K2 + k] = h;
        Bt2[(size_t)n * K2 + K + k] = l;
    }
}

// ================= bf16x3 mma.sync GEMM (R7 config) =========================
// mode 0: plain fp32 C store.
// mode 1: fused QKV epilogue — RMSNorm + RoPE + bf16 hi/lo split, writing
//         q2/k2/v2 [B*H, T, 256] directly (no fp32 qkv buffer).
#define GBM 128
#define GBN 128
#define GBK 64
#define GSTRIDE 72                    // bf16 elems per smem row (144 B, padded)
#define GST_BYTES (128 * GSTRIDE * 2) // 18432 per operand per stage
#define GSA(s) ((s) * GST_BYTES)
#define GSB(s) (2 * GST_BYTES + (s) * GST_BYTES)
#define GEMM_SMEM_BYTES (4 * GST_BYTES)   // 73728 (>= 128*132*4 epilogue tile)

__global__ __launch_bounds__(256, 2) void gemm_bf16x3_kernel(
    const __nv_bfloat16* __restrict__ A2, const __nv_bfloat16* __restrict__ B2,
    float* __restrict__ Cm, int M, int N, int K, int mode,
    const float* __restrict__ qw, const float* __restrict__ kw,
    const float* __restrict__ ct, const float* __restrict__ st,
    __nv_bfloat16* __restrict__ Q2, __nv_bfloat16* __restrict__ K2o,
    __nv_bfloat16* __restrict__ V2)
{
    extern __shared__ char gsm[];
    const uint32_t sb = smem_u32_of(gsm);
    const int tid = threadIdx.x;
    const int lane = tid & 31, wid = tid >> 5;
    const int warp_m = wid >> 2;
    const int warp_n = wid & 3;
    const int m0 = blockIdx.y * GBM;
    const int n0 = blockIdx.x * GBN;
    const int K2 = 2 * K;
    const int niter = (3 * K) / GBK;

    float acc[4][4][4];
    #pragma unroll
    for (int i = 0; i < 4; i++)
        #pragma unroll
        for (int j = 0; j < 4; j++)
            #pragma unroll
            for (int q = 0; q < 4; q++) acc[i][j][q] = 0.0f;

    auto load_stage = [&](int kt, int s) {
        int kp = kt * GBK;
        int seg = kp >> 11;               // kp / 2048 (K == 2048)
        int koff = kp & (K - 1);
        const __nv_bfloat16* Ap = A2 + (size_t)m0 * K2 + ((seg == 1) ? K : 0) + koff;
        const __nv_bfloat16* Bp = B2 + (size_t)n0 * K2 + ((seg == 2) ? K : 0) + koff;
        #pragma unroll
        for (int u = 0; u < 4; ++u) {
            int idx = u * 256 + tid;
            int r = idx >> 3;
            int c = (idx & 7) * 8;
            cp16(sb + GSA(s) + r * (GSTRIDE * 2) + c * 2, Ap + (size_t)r * K2 + c);
            cp16(sb + GSB(s) + r * (GSTRIDE * 2) + c * 2, Bp + (size_t)r * K2 + c);
        }
    };

    load_stage(0, 0);
    CP_COMMIT();

    for (int kt = 0; kt < niter; ++kt) {
        const int s = kt & 1;
        if (kt + 1 < niter) {
            load_stage(kt + 1, (kt + 1) & 1);
            CP_COMMIT();
            CP_WAIT1();
        } else {
            CP_WAIT0();
        }
        __syncthreads();

        const uint32_t abase = sb + GSA(s);
        const uint32_t bbase = sb + GSB(s);
        const int arow = warp_m * 64 + (lane & 15);
        const int acol = (lane >> 4) << 3;
        const int brow = warp_n * 32 + ((lane >> 4) << 3) + (lane & 7);
        const int bcol = ((lane >> 3) & 1) << 3;

        #pragma unroll
        for (int ks = 0; ks < 4; ++ks) {
            const int kb = ks * 16;
            uint32_t af[4][4], bf[2][4];
            #pragma unroll
            for (int im = 0; im < 4; ++im)
                ldsm4(af[im], abase + (arow + im * 16) * (GSTRIDE * 2)
                                    + (kb + acol) * 2);
            #pragma unroll
            for (int j2 = 0; j2 < 2; ++j2)
                ldsm4(bf[j2], bbase + (brow + j2 * 16) * (GSTRIDE * 2)
                                    + (kb + bcol) * 2);
            #pragma unroll
            for (int im = 0; im < 4; ++im)
                #pragma unroll
                for (int jn = 0; jn < 4; ++jn)
                    mma_bf16(acc[im][jn], af[im],
                             bf[jn >> 1][(jn & 1) * 2],
                             bf[jn >> 1][(jn & 1) * 2 + 1]);
        }
        __syncthreads();
    }

    const int g = lane >> 2, t4 = lane & 3;

    if (mode == 0) {
        // plain fp32 store
        #pragma unroll
        for (int im = 0; im < 4; ++im) {
            const int r0 = m0 + warp_m * 64 + im * 16 + g;
            #pragma unroll
            for (int jn = 0; jn < 4; ++jn) {
                const int col = n0 + warp_n * 32 + jn * 8 + 2 * t4;
                *(float2*)&Cm[(size_t)r0 * N + col] =
                    make_float2(acc[im][jn][0], acc[im][jn][1]);
                *(float2*)&Cm[(size_t)(r0 + 8) * N + col] =
                    make_float2(acc[im][jn][2], acc[im][jn][3]);
            }
        }
        return;
    }

    // ---- mode 1: fused RMSNorm + RoPE + split epilogue ----
    // stage smem is dead after the final mainloop sync; reuse as fp32 tile.
    float* tile = (float*)gsm;             // [128][132]
    #pragma unroll
    for (int im = 0; im < 4; ++im) {
        const int r = warp_m * 64 + im * 16 + g;
        #pragma unroll
        for (int jn = 0; jn < 4; ++jn) {
            const int col = warp_n * 32 + jn * 8 + 2 * t4;
            *(float2*)&tile[r * 132 + col] =
                make_float2(acc[im][jn][0], acc[im][jn][1]);
            *(float2*)&tile[(r + 8) * 132 + col] =
                make_float2(acc[im][jn][2], acc[im][jn][3]);
        }
    }
    __syncthreads();

    // this block covers 128 tokens x one head section (q/k/v) of d=128
    const int sec = n0 >> 11;              // 0=q, 1=k, 2=v
    const int h = (n0 & 2047) >> 7;        // head index
    const int row = tid >> 1;              // 0..127
    const int hf = tid & 1;                // column half: hf*64 .. +64
    const size_t row0 = (size_t)m0 + row;
    const int b = (int)(row0 >> 11);
    const int t = (int)(row0 & 2047);
    const size_t b2 = (((size_t)(b * H_ + h)) * T_ + t) * 256;

    if (sec == 2) {
        // V: plain hi/lo split
        #pragma unroll 8
        for (int j = 0; j < 64; j += 2) {
            int d = hf * 64 + j;
            uint32_t uh, ul;
            pk_hilo(tile[row * 132 + d], tile[row * 132 + d + 1], uh, ul);
            *(uint32_t*)&g_v2[b2 + d]       = uh;
            *(uint32_t*)&g_v2[b2 + 128 + d] = ul;
        }
    } else {
        // sum of squares over the full row (64 local + pair via shfl)
        float ss = 0.0f;
        #pragma unroll 16
        for (int j = 0; j < 64; ++j) {
            float v = tile[row * 132 + hf * 64 + j];
            ss += v * v;
        }
        ss += __shfl_xor_sync(0xffffffffu, ss, 1);
        const float rn = rsqrtf(ss * (1.0f / 128.0f) + EPS_);
        const float* w = (sec == 0) ? qw : kw;
        __nv_bfloat16* outp = (sec == 0) ? Q2 : K2o;
        #pragma unroll 8
        for (int j = 0; j < 64; j += 2) {
            int d = hf * 64 + j;
            int dp = (d < 64) ? d + 64 : d - 64;
            float nv0 = tile[row * 132 + d]     * rn * w[d];
            float nv1 = tile[row * 132 + d + 1] * rn * w[d + 1];
            float np0 = tile[row * 132 + dp]     * rn * w[dp];
            float np1 = tile[row * 132 + dp + 1] * rn * w[dp + 1];
            float rot0 = (d < 64) ? -np0 : np0;
            float rot1 = (d < 64) ? -np1 : np1;
            float c0 = ct[t * D_ + d],     s0 = st[t * D_ + d];
            float c1 = ct[t * D_ + d + 1], s1 = st[t * D_ + d + 1];
            float o0 = nv0 * c0 + rot0 * s0;
            float o1 = nv1 * c1 + rot1 * s1;
            uint32_t uh, ul;
            pk_hilo(o0, o1, uh, ul);
            *(uint32_t*)&outp[b2 + d]       = uh;
            *(uint32_t*)&outp[b2 + 128 + d] = ul;
        }
    }
}

// ===== causal flash attention: warp-local softmax + register-P (FA2) ========
#define FQP 264
#define FOFF_Q 0                       // 64 x 264 x 2 = 33792
#define FOFF_K 33792
#define FOFF_V 67584
#define FL2_SMEM_BYTES 101376

__global__ __launch_bounds__(128, 2) void flash_mma_kernel(
    const __nv_bfloat16* __restrict__ Qg, const __nv_bfloat16* __restrict__ Kg,
    const __nv_bfloat16* __restrict__ Vg, __nv_bfloat16* __restrict__ A2o)
{
    extern __shared__ char fsm[];
    const uint32_t sb = smem_u32_of(fsm);

    const int tid = threadIdx.x;
    const int lane = tid & 31, wm = tid >> 5;       // 4 warps
    const int g = lane >> 2, t4 = lane & 3;
    const int bh = blockIdx.y;
    const int qi = (int)gridDim.x - 1 - (int)blockIdx.x;   // heavy blocks first
    const int q0 = qi << 6;
    const int r0 = wm * 16 + g;

    const __nv_bfloat16* Qp = Qg + ((size_t)bh * T_ + q0) * 256;
    const __nv_bfloat16* Kp = Kg + (size_t)bh * T_ * 256;
    const __nv_bfloat16* Vp = Vg + (size_t)bh * T_ * 256;

    #pragma unroll
    for (int u = 0; u < 16; ++u) {
        int idx = u * 128 + tid;
        int rr = idx >> 5, ch = idx & 31;
        cp16(sb + FOFF_Q + rr * (FQP * 2) + ch * 16,
             Qp + (size_t)rr * 256 + ch * 8);
    }
    CP_COMMIT();

    float po[16][4];
    #pragma unroll
    for (int i = 0; i < 16; i++)
        #pragma unroll
        for (int j = 0; j < 4; j++) po[i][j] = 0.0f;
    float m0c = -3.0e38f, m8c = -3.0e38f;
    float l0 = 0.0f, l8 = 0.0f;

    const int ktiles = qi + 1;
    for (int kt = 0; kt < ktiles; ++kt) {
        const int k0 = kt << 6;
        __syncthreads();

        #pragma unroll
        for (int u = 0; u < 16; ++u) {
            int idx = u * 128 + tid;
            int rr = idx >> 5, ch = idx & 31;
            uint32_t so = rr * (FQP * 2) + ch * 16;
            size_t go = (size_t)(k0 + rr) * 256 + ch * 8;
            cp16(sb + FOFF_K + so, Kp + go);
            cp16(sb + FOFF_V + so, Vp + go);
        }
        CP_COMMIT();
        CP_WAIT0();
        __syncthreads();

        float ps[8][4];
        #pragma unroll
        for (int i = 0; i < 8; i++)
            #pragma unroll
            for (int j = 0; j < 4; j++) ps[i][j] = 0.0f;

        #pragma unroll
        for (int seg = 0; seg < 3; ++seg) {
            const int ao = (seg == 1) ? 128 : 0;
            const int bo = (seg == 2) ? 128 : 0;
            #pragma unroll
            for (int kb = 0; kb < 8; ++kb) {
                const int kc = kb * 16;
                uint32_t af[4];
                ldsm4(af, sb + FOFF_Q +
                      ((wm * 16 + (lane & 15)) * FQP + ao + kc + ((lane >> 4) << 3)) * 2);
                uint32_t bfr[4][4];
                #pragma unroll
                for (int j2 = 0; j2 < 4; ++j2) {
                    int brow = j2 * 16 + ((lane >> 4) << 3) + (lane & 7);
                    ldsm4(bfr[j2], sb + FOFF_K +
                          (brow * FQP + bo + kc + (((lane >> 3) & 1) << 3)) * 2);
                }
                #pragma unroll
                for (int jn = 0; jn < 8; ++jn)
                    mma_bf16(ps[jn], af, bfr[jn >> 1][(jn & 1) * 2],
                             bfr[jn >> 1][(jn & 1) * 2 + 1]);
            }
        }

        const bool diag = (k0 == q0);
        #pragma unroll
        for (int jn = 0; jn < 8; ++jn) {
            int col = jn * 8 + t4 * 2;
            ps[jn][0] *= (1.0f / 128.0f);
            ps[jn][1] *= (1.0f / 128.0f);
            ps[jn][2] *= (1.0f / 128.0f);
            ps[jn][3] *= (1.0f / 128.0f);
            if (diag) {
                if (col     > r0)     ps[jn][0] = -3.0e38f;
                if (col + 1 > r0)     ps[jn][1] = -3.0e38f;
                if (col     > r0 + 8) ps[jn][2] = -3.0e38f;
                if (col + 1 > r0 + 8) ps[jn][3] = -3.0e38f;
            }
        }

        float mr0 = -3.0e38f, mr8 = -3.0e38f;
        #pragma unroll
        for (int jn = 0; jn < 8; ++jn) {
            mr0 = fmaxf(mr0, fmaxf(ps[jn][0], ps[jn][1]));
            mr8 = fmaxf(mr8, fmaxf(ps[jn][2], ps[jn][3]));
        }
        mr0 = fmaxf(mr0, __shfl_xor_sync(0xffffffffu, mr0, 1));
        mr0 = fmaxf(mr0, __shfl_xor_sync(0xffffffffu, mr0, 2));
        mr8 = fmaxf(mr8, __shfl_xor_sync(0xffffffffu, mr8, 1));
        mr8 = fmaxf(mr8, __shfl_xor_sync(0xffffffffu, mr8, 2));

        const float m0n = fmaxf(m0c, mr0);
        const float m8n = fmaxf(m8c, mr8);
        const float al0 = __expf(m0c - m0n);
        const float al8 = __expf(m8c - m8n);
        m0c = m0n; m8c = m8n;

        float se0 = 0.0f, se8 = 0.0f;
        #pragma unroll
        for (int jn = 0; jn < 8; ++jn) {
            ps[jn][0] = __expf(ps[jn][0] - m0n);
            ps[jn][1] = __expf(ps[jn][1] - m0n);
            ps[jn][2] = __expf(ps[jn][2] - m8n);
            ps[jn][3] = __expf(ps[jn][3] - m8n);
            se0 += ps[jn][0] + ps[jn][1];
            se8 += ps[jn][2] + ps[jn][3];
        }
        l0 = l0 * al0 + se0;
        l8 = l8 * al8 + se8;

        #pragma unroll
        for (int jb = 0; jb < 16; ++jb) {
            po[jb][0] *= al0; po[jb][1] *= al0;
            po[jb][2] *= al8; po[jb][3] *= al8;
        }

        #pragma unroll
        for (int kk = 0; kk < 4; ++kk) {
            uint32_t ph[4], pl[4];
            #pragma unroll
            for (int i = 0; i < 4; ++i) {
                int jn = 2 * kk + (i >> 1);
                int p2 = (i & 1) * 2;
                pk_hilo(ps[jn][p2], ps[jn][p2 + 1], ph[i], pl[i]);
            }
            const int vrow = kk * 16 + (((lane >> 3) & 1) << 3) + (lane & 7);
            #pragma unroll
            for (int nb = 0; nb < 8; ++nb) {
                const int vcol = nb * 16 + ((lane >> 4) << 3);
                uint32_t vh[4], vl[4];
                ldsm4t(vh, sb + FOFF_V + (vrow * FQP + vcol) * 2);
                mma_bf16(po[nb * 2],     ph, vh[0], vh[1]);
                mma_bf16(po[nb * 2 + 1], ph, vh[2], vh[3]);
                mma_bf16(po[nb * 2],     pl, vh[0], vh[1]);
                mma_bf16(po[nb * 2 + 1], pl, vh[2], vh[3]);
                ldsm4t(vl, sb + FOFF_V + (vrow * FQP + 128 + vcol) * 2);
                mma_bf16(po[nb * 2],     ph, vl[0], vl[1]);
                mma_bf16(po[nb * 2 + 1], ph, vl[2], vl[3]);
            }
        }
    }

    l0 += __shfl_xor_sync(0xffffffffu, l0, 1);
    l0 += __shfl_xor_sync(0xffffffffu, l0, 2);
    l8 += __shfl_xor_sync(0xffffffffu, l8, 1);
    l8 += __shfl_xor_sync(0xffffffffu, l8, 2);
    const float inv0 = 1.0f / l0;
    const float inv8 = 1.0f / l8;

    const int b = bh >> 4, h = bh & 15;
    #pragma unroll
    for (int jb = 0; jb < 16; ++jb) {
        int dcol = jb * 8 + t4 * 2;
        size_t row0 = (size_t)(b * T_) + q0 + r0;
        float o00 = po[jb][0] * inv0, o01 = po[jb][1] * inv0;
        float o80 = po[jb][2] * inv8, o81 = po[jb][3] * inv8;
        uint32_t uh0, ul0, uh8, ul8;
        pk_hilo(o00, o01, uh0, ul0);
        pk_hilo(o80, o81, uh8, ul8);
        size_t c0 = row0 * (2 * C_) + h * D_ + dcol;
        size_t c8 = (row0 + 8) * (2 * C_) + h * D_ + dcol;
        *(uint32_t*)&A2o[c0]      = uh0;
        *(uint32_t*)&A2o[c0 + C_] = ul0;
        *(uint32_t*)&A2o[c8]      = uh8;
        *(uint32_t*)&A2o[c8 + C_] = ul8;
    }
}

// ---------------- launch --------------------------------------------------
extern "C" void kernel_launch(void* const* d_in, const int* in_sizes, int n_in,
                              void* d_out, int out_size)
{
    const float* x      = (const float*)d_in[0];
    const float* w_qkv  = (const float*)d_in[1];
    const float* w_proj = (const float*)d_in[2];
    const float* qw     = (const float*)d_in[3];
    const float* kw     = (const float*)d_in[4];
    float* out = (float*)d_out;

    float *ct, *st;
    __nv_bfloat16 *q2, *k2, *v2, *a2, *bt2;
    cudaGetSymbolAddress((void**)&q2,  g_q2);
    cudaGetSymbolAddress((void**)&k2,  g_k2);
    cudaGetSymbolAddress((void**)&v2,  g_v2);
    cudaGetSymbolAddress((void**)&ct,  g_cos);
    cudaGetSymbolAddress((void**)&st,  g_sin);
    cudaGetSymbolAddress((void**)&a2,  g_a2);
    cudaGetSymbolAddress((void**)&bt2, g_bt2);

    cudaFuncSetAttribute(flash_mma_kernel,
                         cudaFuncAttributeMaxDynamicSharedMemorySize, FL2_SMEM_BYTES);
    cudaFuncSetAttribute(gemm_bf16x3_kernel,
                         cudaFuncAttributeMaxDynamicSharedMemorySize, GEMM_SMEM_BYTES);

    const int M = B_ * T_;          // 4096
    const int K = C_;               // 2048
    const int N1 = 3 * C_;          // 6144

    // 1) RoPE tables
    rope_table_kernel<<<(T_ * D_ + 255) / 256, 256>>>(ct, st);

    // 2) split x -> a2, split w_qkv^T -> bt2
    split_rows_kernel<<<(int)(((size_t)M * K / 4 + 255) / 256), 256>>>(x, a2, M, K);
    split_trans_kernel<<<dim3(N1 / 32, K / 32), 256>>>(w_qkv, bt2, K, N1);

    // 3) QKV GEMM + fused RMSNorm/RoPE/split epilogue -> q2,k2,v2
    gemm_bf16x3_kernel<<<dim3(N1 / GBN, M / GBM), 256, GEMM_SMEM_BYTES>>>(
        a2, bt2, nullptr, M, N1, K, 1, qw, kw, ct, st, q2, k2, v2);

    // 4) causal flash attention -> writes hi/lo split of y directly into a2
    flash_mma_kernel<<<dim3(T_ / 64, B_ * H_), 128, FL2_SMEM_BYTES>>>(q2, k2, v2, a2);

    // 5) split w_proj^T -> bt2
    split_trans_kernel<<<dim3(C_ / 32, K / 32), 256>>>(w_proj, bt2, K, C_);

    // 6) output projection: [M,K] @ [K,C] (plain fp32 epilogue)
    gemm_bf16x3_kernel<<<dim3(C_ / GBN, M / GBM), 256, GEMM_SMEM_BYTES>>>(
        a2, bt2, out, M, C_, K, 0, nullptr, nullptr, nullptr, nullptr,
        nullptr, nullptr, nullptr);
}

// round 16
// speedup vs baseline: 1.1255x; 1.1255x over previous
#include <cuda_runtime.h>
#include <cuda_bf16.h>
#include <cstdint>
#include <cstddef>

#define B_ 2
#define T_ 2048
#define C_ 2048
#define H_ 16
#define D_ 128
#define EPS_ 1.1920929e-07f

typedef unsigned long long u64t;

// ---------------- mma.sync / ldmatrix / cp.async helpers (sm_80+ portable) --
__device__ __forceinline__ uint32_t smem_u32_of(const void* p) {
    uint32_t a;
    asm("{ .reg .u64 t; cvta.to.shared.u64 t, %1; cvt.u32.u64 %0, t; }"
        : "=r"(a) : "l"(p));
    return a;
}
__device__ __forceinline__ void ldsm4(uint32_t* r, uint32_t addr) {
    asm volatile("ldmatrix.sync.aligned.m8n8.x4.shared.b16 {%0,%1,%2,%3}, [%4];"
        : "=r"(r[0]), "=r"(r[1]), "=r"(r[2]), "=r"(r[3]) : "r"(addr));
}
__device__ __forceinline__ void ldsm4t(uint32_t* r, uint32_t addr) {
    asm volatile("ldmatrix.sync.aligned.m8n8.x4.trans.shared.b16 {%0,%1,%2,%3}, [%4];"
        : "=r"(r[0]), "=r"(r[1]), "=r"(r[2]), "=r"(r[3]) : "r"(addr));
}
__device__ __forceinline__ void mma_bf16(float* c, const uint32_t* a,
                                         uint32_t b0, uint32_t b1) {
    asm volatile(
        "mma.sync.aligned.m16n8k16.row.col.f32.bf16.bf16.f32 "
        "{%0,%1,%2,%3}, {%4,%5,%6,%7}, {%8,%9}, {%0,%1,%2,%3};"
        : "+f"(c[0]), "+f"(c[1]), "+f"(c[2]), "+f"(c[3])
        : "r"(a[0]), "r"(a[1]), "r"(a[2]), "r"(a[3]), "r"(b0), "r"(b1));
}
__device__ __forceinline__ void cp16(uint32_t dst, const void* src) {
    asm volatile("cp.async.cg.shared.global [%0], [%1], 16;"
        :: "r"(dst), "l"(src));
}
#define CP_COMMIT() asm volatile("cp.async.commit_group;" ::: "memory")
#define CP_WAIT1()  asm volatile("cp.async.wait_group 1;" ::: "memory")
#define CP_WAIT0()  asm volatile("cp.async.wait_group 0;" ::: "memory")

// pack two fp32 into bf16x2 hi reg + bf16x2 lo-residual reg
__device__ __forceinline__ void pk_hilo(float a, float b,
                                        uint32_t& h, uint32_t& l) {
    __nv_bfloat16 ha = __float2bfloat16_rn(a);
    __nv_bfloat16 hb = __float2bfloat16_rn(b);
    __nv_bfloat162 hh(ha, hb);
    h = *reinterpret_cast<uint32_t*>(&hh);
    __nv_bfloat162 ll(__float2bfloat16_rn(a - __bfloat162float(ha)),
                      __float2bfloat16_rn(b - __bfloat162float(hb)));
    l = *reinterpret_cast<uint32_t*>(&ll);
}

// ---------------- scratch (static device globals; no runtime alloc) ---------
__device__ float g_qkv[(size_t)B_ * T_ * 3 * C_];        // [B*T, 3C]
// pre-split bf16 hi|lo Q/K/V: [B*H, T, 256] (hi 0..127 | lo 128..255)
__device__ __nv_bfloat16 g_q2[(size_t)B_ * H_ * T_ * 256];
__device__ __nv_bfloat16 g_k2[(size_t)B_ * H_ * T_ * 256];
__device__ __nv_bfloat16 g_v2[(size_t)B_ * H_ * T_ * 256];
__device__ float g_cos[(size_t)T_ * D_];
__device__ float g_sin[(size_t)T_ * D_];
// bf16 split operands: A2 [M, 2K] (hi | lo), Bt2 [N, 2K] (hi | lo), K = 2048
__device__ __nv_bfloat16 g_a2[(size_t)(B_ * T_) * (2 * C_)];        // 4096 x 4096
__device__ __nv_bfloat16 g_bt2[(size_t)(3 * C_) * (2 * C_)];        // 6144 x 4096

// ---------------- RoPE tables (double pow -> fp32, mirrors JAX rounding) ----
__global__ void rope_table_kernel(float* __restrict__ ct, float* __restrict__ st) {
    int idx = blockIdx.x * 256 + threadIdx.x;
    if (idx >= T_ * D_) return;
    int t = idx >> 7;
    int d = idx & 127;
    int j = d & 63;
    double inv = 1.0 / pow(1.0e6, (double)j / 64.0);
    float inv_f = (float)inv;
    float freq = (float)t * inv_f;
    ct[idx] = cosf(freq);
    st[idx] = sinf(freq);
}

// ---------------- bf16 hi/lo split: X[M,K] fp32 -> A2[M,2K] bf16 ------------
__global__ void split_rows_kernel(const float* __restrict__ X,
                                  __nv_bfloat16* __restrict__ A2,
                                  int Mrows, int K)
{
    int idx4 = blockIdx.x * 256 + threadIdx.x;
    size_t base = (size_t)idx4 * 4;
    if (base >= (size_t)Mrows * K) return;
    int r = (int)(base / K);
    int c = (int)(base % K);
    float4 v = *(const float4*)&X[base];
    __nv_bfloat16 h0 = __float2bfloat16_rn(v.x);
    __nv_bfloat16 h1 = __float2bfloat16_rn(v.y);
    __nv_bfloat16 h2 = __float2bfloat16_rn(v.z);
    __nv_bfloat16 h3 = __float2bfloat16_rn(v.w);
    __nv_bfloat16 l0 = __float2bfloat16_rn(v.x - __bfloat162float(h0));
    __nv_bfloat16 l1 = __float2bfloat16_rn(v.y - __bfloat162float(h1));
    __nv_bfloat16 l2 = __float2bfloat16_rn(v.z - __bfloat162float(h2));
    __nv_bfloat16 l3 = __float2bfloat16_rn(v.w - __bfloat162float(h3));
    size_t ob = (size_t)r * (2 * K) + c;
    __nv_bfloat162* ph = (__nv_bfloat162*)&A2[ob];
    __nv_bfloat162* pl = (__nv_bfloat162*)&A2[ob + K];
    ph[0] = __nv_bfloat162(h0, h1); ph[1] = __nv_bfloat162(h2, h3);
    pl[0] = __nv_bfloat162(l0, l1); pl[1] = __nv_bfloat162(l2, l3);
}

// ------- transpose + split: W[K,N] fp32 -> Bt2[N,2K] bf16 (K-major) ---------
__global__ void split_trans_kernel(const float* __restrict__ W,
                                   __nv_bfloat16* __restrict__ Bt2,
                                   int K, int N)
{
    __shared__ float tile[32][33];
    const int tx = threadIdx.x & 31, ty = threadIdx.x >> 5;
    const int n0 = blockIdx.x * 32, k0 = blockIdx.y * 32;
    #pragma unroll
    for (int i = 0; i < 4; ++i)
        tile[ty + i * 8][tx] = W[(size_t)(k0 + ty + i * 8) * N + n0 + tx];
    __syncthreads();
    const int K2 = 2 * K;
    #pragma unroll
    for (int i = 0; i < 4; ++i) {
        int n = n0 + ty + i * 8;
        int k = k0 + tx;
        float v = tile[tx][ty + i * 8];
        __nv_bfloat16 h = __float2bfloat16_rn(v);
        __nv_bfloat16 l = __float2bfloat16_rn(v - __bfloat162float(h));
        Bt2[(size_t)n * K2 + k] = h;
        Bt2[(size_t)n * K2 + K + k] = l;
    }
}

// ================= bf16x3 mma.sync GEMM (R7 config — best known) ============
#define GBM 128
#define GBN 128
#define GBK 64
#define GSTRIDE 72                    // bf16 elems per smem row (144 B, padded)
#define GST_BYTES (128 * GSTRIDE * 2) // 18432 per operand per stage
#define GSA(s) ((s) * GST_BYTES)
#define GSB(s) (2 * GST_BYTES + (s) * GST_BYTES)
#define GEMM_SMEM_BYTES (4 * GST_BYTES)   // 73728

__global__ __launch_bounds__(256, 2) void gemm_bf16x3_kernel(
    const __nv_bfloat16* __restrict__ A2, const __nv_bfloat16* __restrict__ B2,
    float* __restrict__ Cm, int M, int N, int K)
{
    extern __shared__ char gsm[];
    const uint32_t sb = smem_u32_of(gsm);
    const int tid = threadIdx.x;
    const int lane = tid & 31, wid = tid >> 5;
    const int warp_m = wid >> 2;
    const int warp_n = wid & 3;
    const int m0 = blockIdx.y * GBM;
    const int n0 = blockIdx.x * GBN;
    const int K2 = 2 * K;
    const int niter = (3 * K) / GBK;

    float acc[4][4][4];
    #pragma unroll
    for (int i = 0; i < 4; i++)
        #pragma unroll
        for (int j = 0; j < 4; j++)
            #pragma unroll
            for (int q = 0; q < 4; q++) acc[i][j][q] = 0.0f;

    auto load_stage = [&](int kt, int s) {
        int kp = kt * GBK;
        int seg = kp >> 11;               // kp / 2048 (K == 2048)
        int koff = kp & (K - 1);
        const __nv_bfloat16* Ap = A2 + (size_t)m0 * K2 + ((seg == 1) ? K : 0) + koff;
        const __nv_bfloat16* Bp = B2 + (size_t)n0 * K2 + ((seg == 2) ? K : 0) + koff;
        #pragma unroll
        for (int u = 0; u < 4; ++u) {
            int idx = u * 256 + tid;
            int r = idx >> 3;
            int c = (idx & 7) * 8;
            cp16(sb + GSA(s) + r * (GSTRIDE * 2) + c * 2, Ap + (size_t)r * K2 + c);
            cp16(sb + GSB(s) + r * (GSTRIDE * 2) + c * 2, Bp + (size_t)r * K2 + c);
        }
    };

    load_stage(0, 0);
    CP_COMMIT();

    for (int kt = 0; kt < niter; ++kt) {
        const int s = kt & 1;
        if (kt + 1 < niter) {
            load_stage(kt + 1, (kt + 1) & 1);
            CP_COMMIT();
            CP_WAIT1();
        } else {
            CP_WAIT0();
        }
        __syncthreads();

        const uint32_t abase = sb + GSA(s);
        const uint32_t bbase = sb + GSB(s);
        const int arow = warp_m * 64 + (lane & 15);
        const int acol = (lane >> 4) << 3;
        const int brow = warp_n * 32 + ((lane >> 4) << 3) + (lane & 7);
        const int bcol = ((lane >> 3) & 1) << 3;

        #pragma unroll
        for (int ks = 0; ks < 4; ++ks) {
            const int kb = ks * 16;
            uint32_t af[4][4], bf[2][4];
            #pragma unroll
            for (int im = 0; im < 4; ++im)
                ldsm4(af[im], abase + (arow + im * 16) * (GSTRIDE * 2)
                                    + (kb + acol) * 2);
            #pragma unroll
            for (int j2 = 0; j2 < 2; ++j2)
                ldsm4(bf[j2], bbase + (brow + j2 * 16) * (GSTRIDE * 2)
                                    + (kb + bcol) * 2);
            #pragma unroll
            for (int im = 0; im < 4; ++im)
                #pragma unroll
                for (int jn = 0; jn < 4; ++jn)
                    mma_bf16(acc[im][jn], af[im],
                             bf[jn >> 1][(jn & 1) * 2],
                             bf[jn >> 1][(jn & 1) * 2 + 1]);
        }
        __syncthreads();
    }

    const int g = lane >> 2, t4 = lane & 3;
    #pragma unroll
    for (int im = 0; im < 4; ++im) {
        const int r0 = m0 + warp_m * 64 + im * 16 + g;
        #pragma unroll
        for (int jn = 0; jn < 4; ++jn) {
            const int col = n0 + warp_n * 32 + jn * 8 + 2 * t4;
            *(float2*)&Cm[(size_t)r0 * N + col] =
                make_float2(acc[im][jn][0], acc[im][jn][1]);
            *(float2*)&Cm[(size_t)(r0 + 8) * N + col] =
                make_float2(acc[im][jn][2], acc[im][jn][3]);
        }
    }
}

// --------- fused per-head RMSNorm + RoPE + QKV split (pre-split bf16) -------
__global__ void qkv_post_kernel(
    const float* __restrict__ qkv,
    const float* __restrict__ qw, const float* __restrict__ kw,
    const float* __restrict__ ct, const float* __restrict__ st,
    __nv_bfloat16* __restrict__ Qo, __nv_bfloat16* __restrict__ Ko,
    __nv_bfloat16* __restrict__ Vo)
{
    const int h = blockIdx.x, t = blockIdx.y, b = blockIdx.z;
    const int d = threadIdx.x;
    const size_t base = ((size_t)(b * T_ + t)) * (3 * C_);

    float qv = qkv[base + h * D_ + d];
    float kv = qkv[base + C_ + h * D_ + d];
    float vv = qkv[base + 2 * C_ + h * D_ + d];

    __shared__ float sq[128], sk[128], red[8];

    float s2q = qv * qv, s2k = kv * kv;
    #pragma unroll
    for (int o = 16; o; o >>= 1) {
        s2q += __shfl_xor_sync(0xffffffffu, s2q, o);
        s2k += __shfl_xor_sync(0xffffffffu, s2k, o);
    }
    int w = d >> 5;
    if ((d & 31) == 0) { red[w] = s2q; red[4 + w] = s2k; }
    __syncthreads();
    float sumq = red[0] + red[1] + red[2] + red[3];
    float sumk = red[4] + red[5] + red[6] + red[7];
    float rq = rsqrtf(sumq * (1.0f / 128.0f) + EPS_) * qw[d];
    float rk = rsqrtf(sumk * (1.0f / 128.0f) + EPS_) * kw[d];
    sq[d] = qv * rq;
    sk[d] = kv * rk;
    __syncthreads();

    float c = ct[t * D_ + d], s = st[t * D_ + d];
    float qrot = (d < 64) ? -sq[d + 64] : sq[d - 64];
    float krot = (d < 64) ? -sk[d + 64] : sk[d - 64];
    float qo = sq[d] * c + qrot * s;
    float ko = sk[d] * c + krot * s;

    size_t b2 = (((size_t)(b * H_ + h)) * T_ + t) * 256;
    __nv_bfloat16 qh = __float2bfloat16_rn(qo);
    __nv_bfloat16 kh = __float2bfloat16_rn(ko);
    __nv_bfloat16 vh = __float2bfloat16_rn(vv);
    Qo[b2 + d]       = qh;
    Qo[b2 + 128 + d] = __float2bfloat16_rn(qo - __bfloat162float(qh));
    Ko[b2 + d]       = kh;
    Ko[b2 + 128 + d] = __float2bfloat16_rn(ko - __bfloat162float(kh));
    Vo[b2 + d]       = vh;
    Vo[b2 + 128 + d] = __float2bfloat16_rn(vv - __bfloat162float(vh));
}

// ===== causal flash attention: warp-local softmax + register-P (FA2) ========
// 4 warps, each owns 16 q-rows x all 64 k-cols x all 128 d-cols.
// QK^T loads Qhi/Qlo/Khi/Klo fragments ONCE per k-step and issues hh+lh+hl
// from registers (10 LDSM / 24 MMA vs 15 before).
#define FQP 264
#define FOFF_Q 0                       // 64 x 264 x 2 = 33792
#define FOFF_K 33792
#define FOFF_V 67584
#define FL2_SMEM_BYTES 101376

__global__ __launch_bounds__(128, 2) void flash_mma_kernel(
    const __nv_bfloat16* __restrict__ Qg, const __nv_bfloat16* __restrict__ Kg,
    const __nv_bfloat16* __restrict__ Vg, __nv_bfloat16* __restrict__ A2o)
{
    extern __shared__ char fsm[];
    const uint32_t sb = smem_u32_of(fsm);

    const int tid = threadIdx.x;
    const int lane = tid & 31, wm = tid >> 5;       // 4 warps
    const int g = lane >> 2, t4 = lane & 3;
    const int bh = blockIdx.y;
    const int qi = (int)gridDim.x - 1 - (int)blockIdx.x;   // heavy blocks first
    const int q0 = qi << 6;
    const int r0 = wm * 16 + g;                     // thread's rows: r0, r0+8

    const __nv_bfloat16* Qp = Qg + ((size_t)bh * T_ + q0) * 256;
    const __nv_bfloat16* Kp = Kg + (size_t)bh * T_ * 256;
    const __nv_bfloat16* Vp = Vg + (size_t)bh * T_ * 256;

    // prologue: Q tile (64 rows x 256 bf16) via cp.async
    #pragma unroll
    for (int u = 0; u < 16; ++u) {
        int idx = u * 128 + tid;            // 0..2047
        int rr = idx >> 5, ch = idx & 31;
        cp16(sb + FOFF_Q + rr * (FQP * 2) + ch * 16,
             Qp + (size_t)rr * 256 + ch * 8);
    }
    CP_COMMIT();

    float po[16][4];
    #pragma unroll
    for (int i = 0; i < 16; i++)
        #pragma unroll
        for (int j = 0; j < 4; j++) po[i][j] = 0.0f;
    float m0c = -3.0e38f, m8c = -3.0e38f;
    float l0 = 0.0f, l8 = 0.0f;

    const int ktiles = qi + 1;
    for (int kt = 0; kt < ktiles; ++kt) {
        const int k0 = kt << 6;
        __syncthreads();                   // K/V buffers consumed by all warps

        #pragma unroll
        for (int u = 0; u < 16; ++u) {
            int idx = u * 128 + tid;
            int rr = idx >> 5, ch = idx & 31;
            uint32_t so = rr * (FQP * 2) + ch * 16;
            size_t go = (size_t)(k0 + rr) * 256 + ch * 8;
            cp16(sb + FOFF_K + so, Kp + go);
            cp16(sb + FOFF_V + so, Vp + go);
        }
        CP_COMMIT();
        CP_WAIT0();
        __syncthreads();                   // tile (and Q on kt==0) visible

        // ---- S = Q K^T : fused 3-term, fragments loaded once per k-step ----
        float ps[8][4];
        #pragma unroll
        for (int i = 0; i < 8; i++)
            #pragma unroll
            for (int j = 0; j < 4; j++) ps[i][j] = 0.0f;

        const uint32_t qrow_base = sb + FOFF_Q +
            ((wm * 16 + (lane & 15)) * FQP + ((lane >> 4) << 3)) * 2;
        #pragma unroll
        for (int kb = 0; kb < 8; ++kb) {
            const int kc = kb * 16;
            uint32_t afh[4], afl[4];
            ldsm4(afh, qrow_base + kc * 2);
            ldsm4(afl, qrow_base + (128 + kc) * 2);
            uint32_t bh4[4][4], bl4[4][4];
            #pragma unroll
            for (int j2 = 0; j2 < 4; ++j2) {
                int brow = j2 * 16 + ((lane >> 4) << 3) + (lane & 7);
                uint32_t rbase = sb + FOFF_K +
                    (brow * FQP + kc + (((lane >> 3) & 1) << 3)) * 2;
                ldsm4(bh4[j2], rbase);
                ldsm4(bl4[j2], rbase + 128 * 2);
            }
            #pragma unroll
            for (int jn = 0; jn < 8; ++jn) {
                const int j2 = jn >> 1, hb = (jn & 1) * 2;
                mma_bf16(ps[jn], afh, bh4[j2][hb], bh4[j2][hb + 1]);  // hh
                mma_bf16(ps[jn], afl, bh4[j2][hb], bh4[j2][hb + 1]);  // lh
                mma_bf16(ps[jn], afh, bl4[j2][hb], bl4[j2][hb + 1]);  // hl
            }
        }

        // ---- scale + causal mask (registers) ----
        const bool diag = (k0 == q0);
        #pragma unroll
        for (int jn = 0; jn < 8; ++jn) {
            int col = jn * 8 + t4 * 2;
            ps[jn][0] *= (1.0f / 128.0f);
            ps[jn][1] *= (1.0f / 128.0f);
            ps[jn][2] *= (1.0f / 128.0f);
            ps[jn][3] *= (1.0f / 128.0f);
            if (diag) {
                if (col     > r0)     ps[jn][0] = -3.0e38f;
                if (col + 1 > r0)     ps[jn][1] = -3.0e38f;
                if (col     > r0 + 8) ps[jn][2] = -3.0e38f;
                if (col + 1 > r0 + 8) ps[jn][3] = -3.0e38f;
            }
        }

        // ---- warp-local row max ----
        float mr0 = -3.0e38f, mr8 = -3.0e38f;
        #pragma unroll
        for (int jn = 0; jn < 8; ++jn) {
            mr0 = fmaxf(mr0, fmaxf(ps[jn][0], ps[jn][1]));
            mr8 = fmaxf(mr8, fmaxf(ps[jn][2], ps[jn][3]));
        }
        mr0 = fmaxf(mr0, __shfl_xor_sync(0xffffffffu, mr0, 1));
        mr0 = fmaxf(mr0, __shfl_xor_sync(0xffffffffu, mr0, 2));
        mr8 = fmaxf(mr8, __shfl_xor_sync(0xffffffffu, mr8, 1));
        mr8 = fmaxf(mr8, __shfl_xor_sync(0xffffffffu, mr8, 2));

        const float m0n = fmaxf(m0c, mr0);
        const float m8n = fmaxf(m8c, mr8);
        const float al0 = __expf(m0c - m0n);
        const float al8 = __expf(m8c - m8n);
        m0c = m0n; m8c = m8n;

        // ---- exp in registers; accumulate l partials ----
        float se0 = 0.0f, se8 = 0.0f;
        #pragma unroll
        for (int jn = 0; jn < 8; ++jn) {
            ps[jn][0] = __expf(ps[jn][0] - m0n);
            ps[jn][1] = __expf(ps[jn][1] - m0n);
            ps[jn][2] = __expf(ps[jn][2] - m8n);
            ps[jn][3] = __expf(ps[jn][3] - m8n);
            se0 += ps[jn][0] + ps[jn][1];
            se8 += ps[jn][2] + ps[jn][3];
        }
        l0 = l0 * al0 + se0;
        l8 = l8 * al8 + se8;

        // ---- rescale O accumulators ----
        #pragma unroll
        for (int jb = 0; jb < 16; ++jb) {
            po[jb][0] *= al0; po[jb][1] *= al0;
            po[jb][2] *= al8; po[jb][3] *= al8;
        }

        // ---- O += P V : P fragments packed from registers ----
        #pragma unroll
        for (int kk = 0; kk < 4; ++kk) {
            uint32_t ph[4], pl[4];
            #pragma unroll
            for (int i = 0; i < 4; ++i) {
                int jn = 2 * kk + (i >> 1);
                int p2 = (i & 1) * 2;
                pk_hilo(ps[jn][p2], ps[jn][p2 + 1], ph[i], pl[i]);
            }
            const int vrow = kk * 16 + (((lane >> 3) & 1) << 3) + (lane & 7);
            #pragma unroll
            for (int nb = 0; nb < 8; ++nb) {
                const int vcol = nb * 16 + ((lane >> 4) << 3);
                uint32_t vh[4], vl[4];
                ldsm4t(vh, sb + FOFF_V + (vrow * FQP + vcol) * 2);
                mma_bf16(po[nb * 2],     ph, vh[0], vh[1]);
                mma_bf16(po[nb * 2 + 1], ph, vh[2], vh[3]);
                mma_bf16(po[nb * 2],     pl, vh[0], vh[1]);
                mma_bf16(po[nb * 2 + 1], pl, vh[2], vh[3]);
                ldsm4t(vl, sb + FOFF_V + (vrow * FQP + 128 + vcol) * 2);
                mma_bf16(po[nb * 2],     ph, vl[0], vl[1]);
                mma_bf16(po[nb * 2 + 1], ph, vl[2], vl[3]);
            }
        }
    }

    // ---- final row sums ----
    l0 += __shfl_xor_sync(0xffffffffu, l0, 1);
    l0 += __shfl_xor_sync(0xffffffffu, l0, 2);
    l8 += __shfl_xor_sync(0xffffffffu, l8, 1);
    l8 += __shfl_xor_sync(0xffffffffu, l8, 2);
    const float inv0 = 1.0f / l0;
    const float inv8 = 1.0f / l8;

    // ---- epilogue: normalize, hi/lo split, write a2[M, 2K] ----
    const int b = bh >> 4, h = bh & 15;
    #pragma unroll
    for (int jb = 0; jb < 16; ++jb) {
        int dcol = jb * 8 + t4 * 2;
        size_t row0 = (size_t)(b * T_) + q0 + r0;
        float o00 = po[jb][0] * inv0, o01 = po[jb][1] * inv0;
        float o80 = po[jb][2] * inv8, o81 = po[jb][3] * inv8;
        uint32_t uh0, ul0, uh8, ul8;
        pk_hilo(o00, o01, uh0, ul0);
        pk_hilo(o80, o81, uh8, ul8);
        size_t c0 = row0 * (2 * C_) + h * D_ + dcol;
        size_t c8 = (row0 + 8) * (2 * C_) + h * D_ + dcol;
        *(uint32_t*)&A2o[c0]      = uh0;
        *(uint32_t*)&A2o[c0 + C_] = ul0;
        *(uint32_t*)&A2o[c8]      = uh8;
        *(uint32_t*)&A2o[c8 + C_] = ul8;
    }
}

// ---------------- launch --------------------------------------------------
extern "C" void kernel_launch(void* const* d_in, const int* in_sizes, int n_in,
                              void* d_out, int out_size)
{
    const float* x      = (const float*)d_in[0];
    const float* w_qkv  = (const float*)d_in[1];
    const float* w_proj = (const float*)d_in[2];
    const float* qw     = (const float*)d_in[3];
    const float* kw     = (const float*)d_in[4];
    float* out = (float*)d_out;

    float *qkv, *ct, *st;
    __nv_bfloat16 *q2, *k2, *v2, *a2, *bt2;
    cudaGetSymbolAddress((void**)&qkv, g_qkv);
    cudaGetSymbolAddress((void**)&q2,  g_q2);
    cudaGetSymbolAddress((void**)&k2,  g_k2);
    cudaGetSymbolAddress((void**)&v2,  g_v2);
    cudaGetSymbolAddress((void**)&ct,  g_cos);
    cudaGetSymbolAddress((void**)&st,  g_sin);
    cudaGetSymbolAddress((void**)&a2,  g_a2);
    cudaGetSymbolAddress((void**)&bt2, g_bt2);

    cudaFuncSetAttribute(flash_mma_kernel,
                         cudaFuncAttributeMaxDynamicSharedMemorySize, FL2_SMEM_BYTES);
    cudaFuncSetAttribute(gemm_bf16x3_kernel,
                         cudaFuncAttributeMaxDynamicSharedMemorySize, GEMM_SMEM_BYTES);

    const int M = B_ * T_;          // 4096
    const int K = C_;               // 2048
    const int N1 = 3 * C_;          // 6144

    // 1) RoPE tables
    rope_table_kernel<<<(T_ * D_ + 255) / 256, 256>>>(ct, st);

    // 2) split x -> a2, split w_qkv^T -> bt2
    split_rows_kernel<<<(int)(((size_t)M * K / 4 + 255) / 256), 256>>>(x, a2, M, K);
    split_trans_kernel<<<dim3(N1 / 32, K / 32), 256>>>(w_qkv, bt2, K, N1);

    // 3) QKV GEMM (bf16x3 tensor cores): [M,K] @ [K,N1]
    gemm_bf16x3_kernel<<<dim3(N1 / GBN, M / GBM), 256, GEMM_SMEM_BYTES>>>(
        a2, bt2, qkv, M, N1, K);

    // 4) RMSNorm + RoPE + pre-split bf16 hi/lo Q/K/V
    qkv_post_kernel<<<dim3(H_, T_, B_), 128>>>(qkv, qw, kw, ct, st, q2, k2, v2);

    // 5) causal flash attention -> writes hi/lo split of y directly into a2
    flash_mma_kernel<<<dim3(T_ / 64, B_ * H_), 128, FL2_SMEM_BYTES>>>(q2, k2, v2, a2);

    // 6) split w_proj^T -> bt2
    split_trans_kernel<<<dim3(C_ / 32, K / 32), 256>>>(w_proj, bt2, K, C_);

    // 7) output projection: [M,K] @ [K,C]
    gemm_bf16x3_kernel<<<dim3(C_ / GBN, M / GBM), 256, GEMM_SMEM_BYTES>>>(
        a2, bt2, out, M, C_, K);
}